// round 10
// baseline (speedup 1.0000x reference)
#include <cuda_runtime.h>
#include <cstdint>

#define BATCH 1024
#define INF   512
#define OUTF  512
#define BT    64
#define OT    64
#define KT    16
#define NSTAGES   (INF / KT)     // 32
#define MAIN_S    28             // stages done by main CTAs
#define NTILES    128            // 16 b-tiles x 8 o-tiles
#define NMAIN     128
#define NEXTRA    20             // 148 - 128
#define GRID_MAIN 148

typedef unsigned long long ull;

__device__ __forceinline__ float ex2f(float q) {
    float r; asm("ex2.approx.ftz.f32 %0, %1;" : "=f"(r) : "f"(q)); return r;
}
__device__ __forceinline__ ull fma2(ull a, ull b, ull c) {
    ull d; asm("fma.rn.f32x2 %0, %1, %2, %3;" : "=l"(d) : "l"(a), "l"(b), "l"(c)); return d;
}
__device__ __forceinline__ ull pk(float lo, float hi) {
    ull r; asm("mov.b64 %0, {%1, %2};" : "=l"(r) : "f"(lo), "f"(hi)); return r;
}
__device__ __forceinline__ void upk(float& lo, float& hi, ull v) {
    asm("mov.b64 {%0, %1}, %2;" : "=f"(lo), "=f"(hi) : "l"(v));
}

// Scratch (static __device__ globals: allocation-free per harness rules)
// Param per (o,i): float4 {inv = K/s, ty = -K*t/s, wz, wb}, K = sqrt(1/(2ln2)):
// w = x*inv+ty  ->  ex2(-w^2) = exp(-u^2/2);  wz*(u^2-1) = fma(-w^2, -2ln2*wz, -wz)
__device__ float4 g_P[OUTF * INF];
__device__ float  g_Xx[INF * BATCH];      // x transposed [i][b]
__device__ float  g_Xs[INF * BATCH];      // silu(x) transposed [i][b]
__device__ float  g_wav[BATCH * OUTF];    // wavelet sums, stages 0..27
__device__ float  g_part[BATCH * OUTF];   // wavelet partials, stages 28..31

#define PBLOCKS 1024   // OUTF*INF/256
#define TBLOCKS 512    // (INF/32) * (BATCH/32) transpose tiles

// ---------------------------------------------------------------------------
// Fused prep: blocks [0,PBLOCKS) pack params; blocks [PBLOCKS,+TBLOCKS) do a
// 32x32 smem-tiled transpose of x (+silu), coalesced on both sides.
// ---------------------------------------------------------------------------
__global__ void prep_all(const float* __restrict__ x,
                         const float* __restrict__ bw, const float* __restrict__ ww,
                         const float* __restrict__ sc, const float* __restrict__ tr) {
    if (blockIdx.x < PBLOCKS) {
        int idx = blockIdx.x * 256 + threadIdx.x;
        const float K = 0.84936056542f;          // sqrt(1/(2ln2))
        float inv = K * __frcp_rn(sc[idx]);
        float4 p;
        p.x = inv;
        p.y = -tr[idx] * inv;
        p.z = ww[idx];
        p.w = bw[idx];
        g_P[idx] = p;
    } else {
        __shared__ float tX[32][33];
        __shared__ float tS[32][33];
        int bt = blockIdx.x - PBLOCKS;           // 0..511
        int i0 = (bt & 15) * 32;                 // 16 i-tiles
        int b0 = (bt >> 4) * 32;                 // 32 b-tiles
        int tc = threadIdx.x & 31;
        int tr_ = threadIdx.x >> 5;              // 0..7
        #pragma unroll
        for (int j = 0; j < 4; ++j) {
            int r = tr_ + 8 * j;                 // b offset on read
            float v = x[(size_t)(b0 + r) * INF + i0 + tc];
            float e = __expf(-v);
            tX[r][tc] = v;
            tS[r][tc] = v / (1.0f + e);
        }
        __syncthreads();
        #pragma unroll
        for (int j = 0; j < 4; ++j) {
            int r = tr_ + 8 * j;                 // i offset on write
            g_Xx[(size_t)(i0 + r) * BATCH + b0 + tc] = tX[tc][r];
            g_Xs[(size_t)(i0 + r) * BATCH + b0 + tc] = tS[tc][r];
        }
    }
}

// ---------------------------------------------------------------------------
// Wavelet kernel shared tiles (40 KB static)
// ---------------------------------------------------------------------------
__shared__ float4 sP[2][KT][OT];        // 32 KB (swizzled cols)
__shared__ float4 sX[2][KT][BT / 4];    //  8 KB

__device__ __forceinline__ void load_stage(int s, int buf, int b0, int o0, int tid) {
    const int k0 = s * KT;
    #pragma unroll
    for (int j = 0; j < 4; ++j) {
        int idx = j * 256 + tid;
        int k   = idx & 15;
        int o   = idx >> 4;
        const float4* src = &g_P[(size_t)(o0 + o) * INF + (k0 + k)];
        uint32_t dst = (uint32_t)__cvta_generic_to_shared(&sP[buf][k][o ^ (k & 7)]);
        asm volatile("cp.async.cg.shared.global [%0], [%1], 16;\n" :: "r"(dst), "l"(src));
    }
    {
        int k  = tid >> 4;
        int b4 = tid & 15;
        const float* srcx = &g_Xx[(size_t)(k0 + k) * BATCH + b0 + b4 * 4];
        uint32_t dstx = (uint32_t)__cvta_generic_to_shared(&sX[buf][k][b4]);
        asm volatile("cp.async.cg.shared.global [%0], [%1], 16;\n" :: "r"(dstx), "l"(srcx));
    }
    asm volatile("cp.async.commit_group;\n" ::);
}

// Wavelet-only: stages [s_begin, s_end) of tile (b0,o0); writes g_wav or g_part.
__device__ __forceinline__ void run_tile(int b0, int o0, int s_begin, int s_end,
                                         float* __restrict__ dst) {
    const int tid = threadIdx.x;
    const int tb  = tid & 15;        // 16 batch groups (4 b each)
    const int to  = tid >> 4;        // 16 o groups (4 o each)

    float acc[4][4];
    #pragma unroll
    for (int i = 0; i < 4; ++i)
        #pragma unroll
        for (int j = 0; j < 4; ++j) acc[i][j] = 0.0f;

    load_stage(s_begin, 0, b0, o0, tid);
    load_stage(s_begin + 1, 1, b0, o0, tid);

    const float C2N = -1.38629436112f;   // -2*ln2

    #pragma unroll 1
    for (int s = s_begin; s < s_end; ++s) {
        asm volatile("cp.async.wait_group 1;\n" ::);
        __syncthreads();
        const int buf = (s - s_begin) & 1;

        #pragma unroll 8
        for (int k = 0; k < KT; ++k) {
            float4 xa = sX[buf][k][tb];
            float xv[4] = {xa.x, xa.y, xa.z, xa.w};
            #pragma unroll
            for (int oo = 0; oo < 4; ++oo) {
                float4 p = sP[buf][k][(4 * to + oo) ^ (k & 7)];
                float wzC = p.z * C2N;               // -2ln2*wz (hoisted, /4 elems)
                #pragma unroll
                for (int bb = 0; bb < 4; ++bb) {
                    float w  = fmaf(xv[bb], p.x, p.y);     // K*(x-t)/s
                    float qn = w * (-w);                   // -w^2 (free src neg)
                    float e  = ex2f(qn);                   // exp(-u^2/2)
                    float mp = fmaf(qn, wzC, -p.z);        // wz*(u^2-1), free c-neg
                    acc[bb][oo] = fmaf(mp, e, acc[bb][oo]);// wavelet only
                }
            }
        }
        __syncthreads();
        if (s + 2 < s_end) load_stage(s + 2, buf, b0, o0, tid);
        else               asm volatile("cp.async.commit_group;\n" ::);
    }

    #pragma unroll
    for (int bb = 0; bb < 4; ++bb) {
        int b = b0 + 4 * tb + bb;
        float4 r;
        r.x = acc[bb][0]; r.y = acc[bb][1]; r.z = acc[bb][2]; r.w = acc[bb][3];
        *reinterpret_cast<float4*>(dst + (size_t)b * OUTF + o0 + 4 * to) = r;
    }
}

// ---------------------------------------------------------------------------
// Wavelet main: 148 persistent CTAs. CTAs 0..127: tile c, stages 0..27 -> g_wav.
// CTAs 128..147: stages 28..31 of 6-7 tiles each -> g_part.
// ---------------------------------------------------------------------------
__global__ void __launch_bounds__(256)
wkan_main() {
    const int c = blockIdx.x;
    if (c < NMAIN) {
        int b0 = (c & 15) * BT;
        int o0 = (c >> 4) * OT;
        run_tile(b0, o0, 0, MAIN_S, g_wav);
    } else {
        for (int t = c - NMAIN; t < NTILES; t += NEXTRA) {
            int b0 = (t & 15) * BT;
            int o0 = (t >> 4) * OT;
            run_tile(b0, o0, MAIN_S, NSTAGES, g_part);
            __syncthreads();   // smem reuse across tiles
        }
    }
}

// ---------------------------------------------------------------------------
// Base GEMM + final merge: out = silu(x)@BW^T + bias + g_wav + g_part.
// 128 CTAs x 512 threads, 64x64 tile, f32x2 paired over adjacent o.
// W staged LDG->regs->STS transposed to [k][o] so o-pairs are LDS.64.
// ---------------------------------------------------------------------------
__global__ void __launch_bounds__(512)
gemm_final(const float* __restrict__ bw, const float* __restrict__ bias,
           float* __restrict__ out) {
    __shared__ __align__(16) float2 gA[2][KT][32];   // [k][b-pair]  8 KB
    __shared__ __align__(16) float  gW[2][KT][68];   // [k][o] padded 8.7 KB

    const int tid = threadIdx.x;
    const int tb  = tid & 31;          // 32 b-groups x 2 b
    const int to  = tid >> 5;          // 16 o-groups x 4 o (2 pairs)
    const int b0  = (blockIdx.x & 15) * 64;
    const int o0  = (blockIdx.x >> 4) * 64;

    ull acc2[2][2];
    acc2[0][0] = acc2[0][1] = acc2[1][0] = acc2[1][1] = 0ull;

    const int wo = tid >> 2;           // 0..63 (o within tile)  [tid<256]
    const int wk = (tid & 3) * 4;      // k offset 0,4,8,12
    // A loader: 256 threads x 16B = 64 floats per k row (FIX: was 128 thr = half tile)
    const int ak = tid >> 4;           // 0..15 (k)     [tid<256]
    const int ab = tid & 15;           // 0..15 (b/4)
    float4 wreg;
    if (tid < 256)
        wreg = *reinterpret_cast<const float4*>(&bw[(size_t)(o0 + wo) * INF + wk]);
    if (tid < 256) {
        const float* src = &g_Xs[(size_t)ak * BATCH + b0 + 4 * ab];
        uint32_t dst = (uint32_t)__cvta_generic_to_shared(&gA[0][ak][2 * ab]);
        asm volatile("cp.async.cg.shared.global [%0], [%1], 16;\n" :: "r"(dst), "l"(src));
    }
    asm volatile("cp.async.commit_group;\n" ::);

    #pragma unroll 1
    for (int s = 0; s < NSTAGES; ++s) {
        const int buf = s & 1;
        if (tid < 256) {                      // W(s): regs -> smem transposed
            gW[buf][wk + 0][wo] = wreg.x;
            gW[buf][wk + 1][wo] = wreg.y;
            gW[buf][wk + 2][wo] = wreg.z;
            gW[buf][wk + 3][wo] = wreg.w;
        }
        if (s + 1 < NSTAGES && tid < 256)     // prefetch W(s+1) early (LDG hides under compute)
            wreg = *reinterpret_cast<const float4*>(
                &bw[(size_t)(o0 + wo) * INF + (s + 1) * KT + wk]);
        asm volatile("cp.async.wait_group 0;\n" ::);
        __syncthreads();
        if (s + 1 < NSTAGES && tid < 256) {   // A(s+1) into other buffer
            const float* src = &g_Xs[(size_t)((s + 1) * KT + ak) * BATCH + b0 + 4 * ab];
            uint32_t dst = (uint32_t)__cvta_generic_to_shared(&gA[buf ^ 1][ak][2 * ab]);
            asm volatile("cp.async.cg.shared.global [%0], [%1], 16;\n" :: "r"(dst), "l"(src));
        }
        asm volatile("cp.async.commit_group;\n" ::);

        #pragma unroll
        for (int k = 0; k < KT; ++k) {
            float2 a = gA[buf][k][tb];
            ull ax = pk(a.x, a.x);
            ull ay = pk(a.y, a.y);
            #pragma unroll
            for (int j = 0; j < 2; ++j) {
                ull w2 = *reinterpret_cast<const ull*>(&gW[buf][k][4 * to + 2 * j]);
                acc2[0][j] = fma2(ax, w2, acc2[0][j]);
                acc2[1][j] = fma2(ay, w2, acc2[1][j]);
            }
        }
        // no trailing sync needed: next-iter wait+sync precedes any reuse of this buffer
    }

    // Epilogue: out = gemm + bias + g_wav + g_part
    float4 bv = *reinterpret_cast<const float4*>(&bias[o0 + 4 * to]);
    #pragma unroll
    for (int bb = 0; bb < 2; ++bb) {
        int b = b0 + 2 * tb + bb;
        size_t off = (size_t)b * OUTF + o0 + 4 * to;
        float4 wv = *reinterpret_cast<const float4*>(&g_wav[off]);
        float4 pv = *reinterpret_cast<const float4*>(&g_part[off]);
        float l0, h0, l1, h1;
        upk(l0, h0, acc2[bb][0]);
        upk(l1, h1, acc2[bb][1]);
        float4 r;
        r.x = l0 + bv.x + wv.x + pv.x;
        r.y = h0 + bv.y + wv.y + pv.y;
        r.z = l1 + bv.z + wv.z + pv.z;
        r.w = h1 + bv.w + wv.w + pv.w;
        *reinterpret_cast<float4*>(&out[off]) = r;
    }
}

// ---------------------------------------------------------------------------
extern "C" void kernel_launch(void* const* d_in, const int* in_sizes, int n_in,
                              void* d_out, int out_size) {
    (void)in_sizes; (void)n_in; (void)out_size;
    const float* x    = (const float*)d_in[0];
    const float* bw   = (const float*)d_in[1];
    const float* ww   = (const float*)d_in[2];
    const float* sc   = (const float*)d_in[3];
    const float* tr   = (const float*)d_in[4];
    const float* bias = (const float*)d_in[5];
    float* out = (float*)d_out;

    prep_all<<<PBLOCKS + TBLOCKS, 256>>>(x, bw, ww, sc, tr);
    wkan_main<<<GRID_MAIN, 256>>>();
    gemm_final<<<NTILES, 512>>>(bw, bias, out);
}